// round 14
// baseline (speedup 1.0000x reference)
#include <cuda_runtime.h>
#include <cuda_fp16.h>
#include <cstdint>
#include <stdint.h>
#include <math.h>

using u32 = unsigned int;

// Problem constants
#define BB 2
#define SS 1024
#define DD 2048
#define HH 16
#define DHD 128
#define MM (BB * SS)   // 2048 rows

// ---------------------------------------------------------------------------
// Scratch (__device__ globals; allocation-free per harness rules)
// ---------------------------------------------------------------------------
__device__ __half g_wq[DD * DD];
__device__ __half g_wk[DD * DD];
__device__ __half g_wv[DD * DD];
__device__ __half g_wo[DD * DD];
__device__ __half g_xh[MM * DD];      // hidden_states fp16
__device__ __half g_attnh[MM * DD];   // attention output fp16
__device__ __half g_qh[MM * DD];      // Q (post norm+rope, in place)
__device__ __half g_kh[MM * DD];      // K (post norm+rope, in place)
__device__ __half g_vh[MM * DD];      // V (fp16)

// ---------------------------------------------------------------------------
// PTX helpers
// ---------------------------------------------------------------------------
__device__ __forceinline__ uint4 ldsm_x4(u32 addr) {
    uint4 r;
    asm volatile("ldmatrix.sync.aligned.m8n8.x4.shared.b16 {%0,%1,%2,%3}, [%4];"
                 : "=r"(r.x), "=r"(r.y), "=r"(r.z), "=r"(r.w) : "r"(addr));
    return r;
}
__device__ __forceinline__ uint4 ldsm_x4_t(u32 addr) {
    uint4 r;
    asm volatile("ldmatrix.sync.aligned.m8n8.x4.trans.shared.b16 {%0,%1,%2,%3}, [%4];"
                 : "=r"(r.x), "=r"(r.y), "=r"(r.z), "=r"(r.w) : "r"(addr));
    return r;
}
__device__ __forceinline__ void mma16816(float* c, const uint4& a, u32 b0, u32 b1) {
    asm volatile(
        "mma.sync.aligned.m16n8k16.row.col.f32.f16.f16.f32 "
        "{%0,%1,%2,%3}, {%4,%5,%6,%7}, {%8,%9}, {%0,%1,%2,%3};"
        : "+f"(c[0]), "+f"(c[1]), "+f"(c[2]), "+f"(c[3])
        : "r"(a.x), "r"(a.y), "r"(a.z), "r"(a.w), "r"(b0), "r"(b1));
}
__device__ __forceinline__ void cp16(u32 dst, const void* src) {
    asm volatile("cp.async.cg.shared.global [%0], [%1], 16;" :: "r"(dst), "l"(src));
}
#define CP_COMMIT() asm volatile("cp.async.commit_group;")
#define CP_WAIT(N)  asm volatile("cp.async.wait_group %0;" :: "n"(N))

__device__ __forceinline__ u32 h2u(float a, float b) {
    __half2 h = __floats2half2_rn(a, b);
    return *reinterpret_cast<u32*>(&h);
}
__device__ __forceinline__ u32 ex2_h2(u32 v) {
    asm("ex2.approx.f16x2 %0, %0;" : "+r"(v));
    return v;
}
__device__ __forceinline__ u32 smaddr(const void* p) {
    return (u32)__cvta_generic_to_shared(p);
}

// ---------------------------------------------------------------------------
// Kernel 1: converts. blockIdx.y remapped via m0/m1/m2 params:
//   0..3 -> weights wq/wk/wv/wo, 4 -> hidden_states.
// ---------------------------------------------------------------------------
__global__ __launch_bounds__(256) void convert_all(
    const int* __restrict__ wq, const int* __restrict__ wk,
    const int* __restrict__ wv, const int* __restrict__ wo,
    const float* __restrict__ wq_s, const float* __restrict__ wk_s,
    const float* __restrict__ wv_s, const float* __restrict__ wo_s,
    const float* __restrict__ x, int m0, int m1, int m2) {
    const int y = (blockIdx.y == 0) ? m0 : (blockIdx.y == 1) ? m1 : m2;
    const int i = (blockIdx.x * 256 + threadIdx.x) * 16;
    __align__(16) __half h[16];
    if (y == 4) {
#pragma unroll
        for (int u = 0; u < 4; u++) {
            float4 a = *(const float4*)(x + i + 4 * u);
            h[4 * u + 0] = __float2half(a.x);
            h[4 * u + 1] = __float2half(a.y);
            h[4 * u + 2] = __float2half(a.z);
            h[4 * u + 3] = __float2half(a.w);
        }
        *(uint4*)(g_xh + i)     = *(const uint4*)h;
        *(uint4*)(g_xh + i + 8) = *(const uint4*)(h + 8);
        return;
    }
    const int*   w = (y == 0) ? wq : (y == 1) ? wk : (y == 2) ? wv : wo;
    const float* s = (y == 0) ? wq_s : (y == 1) ? wk_s : (y == 2) ? wv_s : wo_s;
    __half*    out = (y == 0) ? g_wq : (y == 1) ? g_wk : (y == 2) ? g_wv : g_wo;
    float sc = s[i >> 11];
#pragma unroll
    for (int u = 0; u < 4; u++) {
        int4 a = *(const int4*)(w + i + 4 * u);
        h[4 * u + 0] = __float2half((float)a.x * sc);
        h[4 * u + 1] = __float2half((float)a.y * sc);
        h[4 * u + 2] = __float2half((float)a.z * sc);
        h[4 * u + 3] = __float2half((float)a.w * sc);
    }
    *(uint4*)(out + i)     = *(const uint4*)h;
    *(uint4*)(out + i + 8) = *(const uint4*)(h + 8);
}

// ---------------------------------------------------------------------------
// HGEMM core (R6 measured-best): 128x128 tile, BK=64, 3-stage cp.async,
// 256 threads, warp tile 64x32, 2 CTAs/SM.
// ---------------------------------------------------------------------------
#define HG_STG 9216                       // halfs per matrix per stage (128*72)
#define HG_STAGE_BYTES (2 * HG_STG * 2)   // A+B, 36864 B
#define HG_BYTES (3 * HG_STAGE_BYTES)     // 110592 B

template <typename OutT>
__device__ __forceinline__ void store2(OutT* p, float a, float b);
template <> __device__ __forceinline__ void store2<float>(float* p, float a, float b) {
    *(float2*)p = make_float2(a, b);
}
template <> __device__ __forceinline__ void store2<__half>(__half* p, float a, float b) {
    *(__half2*)p = __floats2half2_rn(a, b);
}

template <typename OutT>
__device__ __forceinline__ void hgemm_body(const __half* __restrict__ A,
                                           const __half* __restrict__ B,
                                           OutT* __restrict__ C,
                                           __half* hsm, int bm, int bn) {
    const u32 smb = smaddr(hsm);
    const int t = threadIdx.x, warp = t >> 5, lane = t & 31;
    const int wm = (warp & 1) * 64, wn = (warp >> 1) * 32;
    const int lr = lane & 7, g = lane >> 3;
    const u32 aOff = (u32)(((wm + lr + (g & 1) * 8) * 72 + (g >> 1) * 8) * 2);
    const u32 bOff = (u32)(((wn + lr + (g >> 1) * 8) * 72 + (g & 1) * 8) * 2);

    float c[4][4][4];
#pragma unroll
    for (int mi = 0; mi < 4; mi++)
#pragma unroll
        for (int ni = 0; ni < 4; ni++)
#pragma unroll
            for (int e = 0; e < 4; e++) c[mi][ni][e] = 0.f;

    auto load_stage = [&](int st, int k0) {
        u32 sb = smb + (u32)(st * HG_STAGE_BYTES);
#pragma unroll
        for (int i = 0; i < 4; i++) {
            int id = t + 256 * i;
            int r = id >> 3, cc = id & 7;
            cp16(sb + (u32)((r * 72 + cc * 8) * 2),
                 A + (size_t)(bm + r) * DD + k0 + cc * 8);
            cp16(sb + (u32)(HG_STG * 2) + (u32)((r * 72 + cc * 8) * 2),
                 B + (size_t)(bn + r) * DD + k0 + cc * 8);
        }
    };

    load_stage(0, 0);  CP_COMMIT();
    load_stage(1, 64); CP_COMMIT();

    for (int kt = 0; kt < 32; kt++) {
        if (kt < 31) { CP_WAIT(1); } else { CP_WAIT(0); }
        __syncthreads();
        if (kt + 2 < 32) { load_stage((kt + 2) % 3, (kt + 2) * 64); CP_COMMIT(); }

        u32 ab = smb + (u32)((kt % 3) * HG_STAGE_BYTES) + aOff;
        u32 bb = smb + (u32)((kt % 3) * HG_STAGE_BYTES + HG_STG * 2) + bOff;
#pragma unroll
        for (int ks = 0; ks < 64; ks += 16) {
            uint4 af[4], bf[2];
#pragma unroll
            for (int mi = 0; mi < 4; mi++)
                af[mi] = ldsm_x4(ab + (u32)((mi * 16 * 72 + ks) * 2));
#pragma unroll
            for (int np = 0; np < 2; np++)
                bf[np] = ldsm_x4(bb + (u32)((np * 16 * 72 + ks) * 2));
#pragma unroll
            for (int mi = 0; mi < 4; mi++)
#pragma unroll
                for (int np = 0; np < 2; np++) {
                    mma16816(c[mi][np * 2 + 0], af[mi], bf[np].x, bf[np].y);
                    mma16816(c[mi][np * 2 + 1], af[mi], bf[np].z, bf[np].w);
                }
        }
    }

    const int r0 = bm + wm + (lane >> 2);
    const int cb = bn + wn + (lane & 3) * 2;
#pragma unroll
    for (int mi = 0; mi < 4; mi++)
#pragma unroll
        for (int ni = 0; ni < 4; ni++) {
            int row = r0 + mi * 16, col = cb + ni * 8;
            store2<OutT>(C + (size_t)row * DD + col, c[mi][ni][0], c[mi][ni][1]);
            store2<OutT>(C + (size_t)(row + 8) * DD + col, c[mi][ni][2], c[mi][ni][3]);
        }
}

// Kernel 2a: full Q/K GEMM (z: 0=Q, 1=K; fp16 out)
__global__ __launch_bounds__(256, 2) void hgemm_qk() {
    extern __shared__ __half hsm[];
    const int z = blockIdx.z;
    const __half* B = (z == 0) ? g_wq : g_wk;
    __half*       C = (z == 0) ? g_qh : g_kh;
    hgemm_body<__half>(g_xh, B, C, hsm, blockIdx.y * 128, blockIdx.x * 128);
}

// Kernel 2b: V GEMM (fp16 out; full M)
__global__ __launch_bounds__(256, 2) void hgemm_v() {
    extern __shared__ __half hsm[];
    hgemm_body<__half>(g_xh, g_wv, g_vh, hsm, blockIdx.y * 128, blockIdx.x * 128);
}

// Kernel 2c: O-projection GEMM for one batch half (fp32 out)
__global__ __launch_bounds__(256, 2) void hgemm_o(float* __restrict__ C, int bm0) {
    extern __shared__ __half hsm[];
    hgemm_body<float>(g_attnh, g_wo, C, hsm, bm0 + blockIdx.y * 128, blockIdx.x * 128);
}

// ---------------------------------------------------------------------------
// Kernel 3: RMSNorm + RoPE (full), fp16 in/out, in place on g_qh / g_kh.
// ---------------------------------------------------------------------------
__global__ __launch_bounds__(256) void norm_rope(const float* __restrict__ cosT,
                                                 const float* __restrict__ sinT,
                                                 const float* __restrict__ qn_w,
                                                 const float* __restrict__ kn_w) {
    __half* x       = (blockIdx.y == 0) ? g_qh : g_kh;
    const float* w  = (blockIdx.y == 0) ? qn_w : kn_w;
    const int row = blockIdx.x;
    const int s   = row & (SS - 1);
    const int t   = threadIdx.x;

    __shared__ float buf[DD];
    __shared__ float red[8];

    __half* xr = x + (size_t)row * DD;
    float ss = 0.f;
    {
        int i = t * 8;
        uint4 raw = *(const uint4*)(xr + i);
        const __half* hp = (const __half*)&raw;
#pragma unroll
        for (int j = 0; j < 8; j++) {
            float v = __half2float(hp[j]);
            buf[i + j] = v;
            ss += v * v;
        }
    }
#pragma unroll
    for (int off = 16; off; off >>= 1) ss += __shfl_xor_sync(0xffffffffu, ss, off);
    if ((t & 31) == 0) red[t >> 5] = ss;
    __syncthreads();
    float tot = 0.f;
#pragma unroll
    for (int wI = 0; wI < 8; wI++) tot += red[wI];
    const float inv = rsqrtf(tot * (1.0f / DD) + 1e-6f);

#pragma unroll
    for (int u = 0; u < 4; u++) {
        int p  = t + u * 256;
        int hh = p >> 6;
        int i  = p & 63;
        int d1 = hh * DHD + i;
        int d2 = d1 + 64;
        float y1 = buf[d1] * inv * w[d1];
        float y2 = buf[d2] * inv * w[d2];
        float c1 = cosT[s * DHD + i],      s1 = sinT[s * DHD + i];
        float c2 = cosT[s * DHD + 64 + i], s2 = sinT[s * DHD + 64 + i];
        xr[d1] = __float2half(y1 * c1 - y2 * s1);
        xr[d2] = __float2half(y2 * c2 + y1 * s2);
    }
}

// ---------------------------------------------------------------------------
// Kernel 4: flash-attention (R11) for one batch. S-prefetch pipeline,
// fp16x2 ex2 softmax, mma row-sums. K 3-ring, V 2-ring, 96 KB smem, 128 thr.
// ---------------------------------------------------------------------------
#define FA_TILE_HALFS (64 * 128)                 // 8192
#define FA_KOFF FA_TILE_HALFS                    // after Q
#define FA_VOFF (FA_TILE_HALFS * 4)              // after Q + 3 K slots
#define FA_BYTES (FA_TILE_HALFS * 6 * 2)         // 98304

__device__ __forceinline__ void fa_load_tile(u32 base, const __half* src,
                                             int kt, int t) {
#pragma unroll
    for (int i = 0; i < 8; i++) {
        int id = t + 128 * i;
        int r = id >> 4, cc = id & 15;
        u32 off = (u32)(((r * 128) + ((cc ^ (r & 7)) << 3)) << 1);
        cp16(base + off, src + (size_t)(kt * 64 + r) * DD + cc * 8);
    }
}

__global__ __launch_bounds__(128) void flash_attn(const int* __restrict__ lengths,
                                                  int b) {
    extern __shared__ __half fsm[];
    const u32 smb = smaddr(fsm);

    const int qt = blockIdx.x, h = blockIdx.y;
    const int t = threadIdx.x, warp = t >> 5, lane = t & 31;
    const int lr = lane & 7, g = lane >> 3;
    const int len = lengths[b];
    const int s0  = qt * 64;
    const int nkt = (len + 63) >> 6;

    const __half* qg = g_qh + (size_t)(b * SS) * DD + h * DHD;
    const __half* kg = g_kh + (size_t)(b * SS) * DD + h * DHD;
    const __half* vg = g_vh + (size_t)(b * SS) * DD + h * DHD;

    // prologue: group A = {Q, K0, V0, K1}, group B = {V1}
#pragma unroll
    for (int i = 0; i < 8; i++) {
        int id = t + 128 * i;
        int r = id >> 4, cc = id & 15;
        u32 off = (u32)(((r * 128) + ((cc ^ (r & 7)) << 3)) << 1);
        cp16(smb + off, qg + (size_t)(s0 + r) * DD + cc * 8);
    }
    fa_load_tile(smb + (u32)(FA_KOFF * 2), kg, 0, t);
    fa_load_tile(smb + (u32)(FA_VOFF * 2), vg, 0, t);
    if (nkt > 1) fa_load_tile(smb + (u32)((FA_KOFF + FA_TILE_HALFS) * 2), kg, 1, t);
    CP_COMMIT();
    if (nkt > 1) {
        fa_load_tile(smb + (u32)((FA_VOFF + FA_TILE_HALFS) * 2), vg, 1, t);
        CP_COMMIT();
    }

    const int qrow = 16 * warp + lr + (g & 1) * 8, qx = qrow & 7;
    const int krow = lr + (g >> 1) * 8, kcol = g & 1, kx = krow & 7;
    const int vrow = lr + (g & 1) * 8, vcol = g >> 1, vx = vrow & 7;

    CP_WAIT(1);
    __syncthreads();

    uint4 qf[8];
#pragma unroll
    for (int ks = 0; ks < 8; ks++)
        qf[ks] = ldsm_x4(smb + (u32)(((qrow * 128) +
                          (((2 * ks + (g >> 1)) ^ qx) << 3)) << 1));

    auto compute_S = [&](int kt, float (*s)[4]) {
        const u32 kbase = smb + (u32)((FA_KOFF + (kt % 3) * FA_TILE_HALFS) * 2);
#pragma unroll
        for (int j = 0; j < 8; j++)
#pragma unroll
            for (int e = 0; e < 4; e++) s[j][e] = 0.f;
#pragma unroll
        for (int ks = 0; ks < 8; ks++) {
#pragma unroll
            for (int np = 0; np < 4; np++) {
                uint4 bf = ldsm_x4(kbase + (u32)((((16 * np + krow) * 128) +
                                    (((2 * ks + kcol) ^ kx) << 3)) << 1));
                mma16816(s[2 * np],     qf[ks], bf.x, bf.y);
                mma16816(s[2 * np + 1], qf[ks], bf.z, bf.w);
            }
        }
    };

    float o[16][4];
#pragma unroll
    for (int j2 = 0; j2 < 16; j2++)
#pragma unroll
        for (int e = 0; e < 4; e++) o[j2][e] = 0.f;
    float m0 = -1e30f, m1 = -1e30f, l0 = 0.f, l1 = 0.f;
    const float scl = 0.12751784766914164f;   // log2(e)/sqrt(128)
    const u32 ONES2 = 0x3C003C00u;            // half2(1.0, 1.0)

    float s_cur[8][4], s_next[8][4];
    compute_S(0, s_cur);

    for (int kt = 0; kt < nkt; kt++) {
        CP_WAIT(1);
        __syncthreads();
        if (kt + 2 < nkt) {
            fa_load_tile(smb + (u32)((FA_KOFF + ((kt + 2) % 3) * FA_TILE_HALFS) * 2),
                         kg, kt + 2, t);
            CP_COMMIT();
        }
        if (kt + 1 < nkt) compute_S(kt + 1, s_next);

        // ---- mask + online softmax on s_cur (base-2, fp16x2 ex2) ----
        const int cb = kt * 64 + 2 * (lane & 3);
        float mx0 = -1e30f, mx1 = -1e30f;
#pragma unroll
        for (int j = 0; j < 8; j++) {
            int c0 = cb + 8 * j;
            s_cur[j][0] = (c0 < len)     ? s_cur[j][0] * scl : -1e30f;
            s_cur[j][1] = (c0 + 1 < len) ? s_cur[j][1] * scl : -1e30f;
            s_cur[j][2] = (c0 < len)     ? s_cur[j][2] * scl : -1e30f;
            s_cur[j][3] = (c0 + 1 < len) ? s_cur[j][3] * scl : -1e30f;
            mx0 = fmaxf(mx0, fmaxf(s_cur[j][0], s_cur[j][1]));
            mx1 = fmaxf(mx1, fmaxf(s_cur[j][2], s_cur[j][3]));
        }
        mx0 = fmaxf(mx0, __shfl_xor_sync(0xffffffffu, mx0, 1));
        mx0 = fmaxf(mx0, __shfl_xor_sync(0xffffffffu, mx0, 2));
        mx1 = fmaxf(mx1, __shfl_xor_sync(0xffffffffu, mx1, 1));
        mx1 = fmaxf(mx1, __shfl_xor_sync(0xffffffffu, mx1, 2));

        float mn0 = fmaxf(m0, mx0), mn1 = fmaxf(m1, mx1);
        float al0 = exp2f(m0 - mn0), al1 = exp2f(m1 - mn1);

        u32 pf[8][2];
#pragma unroll
        for (int j = 0; j < 8; j++) {
            pf[j][0] = ex2_h2(h2u(s_cur[j][0] - mn0, s_cur[j][1] - mn0));
            pf[j][1] = ex2_h2(h2u(s_cur[j][2] - mn1, s_cur[j][3] - mn1));
        }

        // row sums of P via tensor core (B = ones)
        float lacc[4] = {0.f, 0.f, 0.f, 0.f};
#pragma unroll
        for (int k2 = 0; k2 < 4; k2++) {
            uint4 a;
            a.x = pf[2 * k2][0];     a.y = pf[2 * k2][1];
            a.z = pf[2 * k2 + 1][0]; a.w = pf[2 * k2 + 1][1];
            mma16816(lacc, a, ONES2, ONES2);
        }
        l0 = l0 * al0 + lacc[0];
        l1 = l1 * al1 + lacc[2];
        m0 = mn0; m1 = mn1;
#pragma unroll
        for (int j2 = 0; j2 < 16; j2++) {
            o[j2][0] *= al0; o[j2][1] *= al0;
            o[j2][2] *= al1; o[j2][3] *= al1;
        }

        // ---- O += P V (V slot kt&1) ----
        const u32 vbase = smb + (u32)((FA_VOFF + (kt & 1) * FA_TILE_HALFS) * 2);
#pragma unroll
        for (int k2 = 0; k2 < 4; k2++) {
            uint4 a;
            a.x = pf[2 * k2][0];     a.y = pf[2 * k2][1];
            a.z = pf[2 * k2 + 1][0]; a.w = pf[2 * k2 + 1][1];
#pragma unroll
            for (int np = 0; np < 8; np++) {
                uint4 bf = ldsm_x4_t(vbase + (u32)((((16 * k2 + vrow) * 128) +
                                     (((2 * np + vcol) ^ vx) << 3)) << 1));
                mma16816(o[2 * np],     a, bf.x, bf.y);
                mma16816(o[2 * np + 1], a, bf.z, bf.w);
            }
        }

        __syncthreads();    // all PV reads of V slot kt&1 done
        if (kt + 2 < nkt) {
            fa_load_tile(smb + (u32)((FA_VOFF + (kt & 1) * FA_TILE_HALFS) * 2),
                         vg, kt + 2, t);
            CP_COMMIT();
        }
        if (kt + 1 < nkt) {
#pragma unroll
            for (int j = 0; j < 8; j++)
#pragma unroll
                for (int e = 0; e < 4; e++) s_cur[j][e] = s_next[j][e];
        }
    }

    const float il0 = 1.f / l0, il1 = 1.f / l1;
    const int r0 = s0 + 16 * warp + (lane >> 2);
    __half* ob = g_attnh + (size_t)(b * SS) * DD + h * DHD;
#pragma unroll
    for (int j2 = 0; j2 < 16; j2++) {
        int col = 8 * j2 + 2 * (lane & 3);
        *(__half2*)(ob + (size_t)r0 * DD + col) =
            __floats2half2_rn(o[j2][0] * il0, o[j2][1] * il0);
        *(__half2*)(ob + (size_t)(r0 + 8) * DD + col) =
            __floats2half2_rn(o[j2][2] * il1, o[j2][3] * il1);
    }
}

// ---------------------------------------------------------------------------
// Launch: R12 structure + FA/O batch-split overlap.
//   M: conv(wq,wk,x) -> QK(full) -> norm(full) -> [eV] FA_b0 -> [eC] O_b0
//        -> [eFA1] O_b1
//   B: conv(wv) -> [eX] Vgemm(eV) -> [eFA0] FA_b1 -> eFA1
//   C: conv(wo) -> eC
// ---------------------------------------------------------------------------
extern "C" void kernel_launch(void* const* d_in, const int* in_sizes, int n_in,
                              void* d_out, int out_size) {
    const float* x     = (const float*)d_in[0];
    const float* wq_s  = (const float*)d_in[1];
    const float* wk_s  = (const float*)d_in[2];
    const float* wv_s  = (const float*)d_in[3];
    const float* wo_s  = (const float*)d_in[4];
    const float* qn_w  = (const float*)d_in[5];
    const float* kn_w  = (const float*)d_in[6];
    const float* cosT  = (const float*)d_in[7];
    const float* sinT  = (const float*)d_in[8];
    const int*   wq    = (const int*)d_in[9];
    const int*   wk    = (const int*)d_in[10];
    const int*   wv    = (const int*)d_in[11];
    const int*   wo    = (const int*)d_in[12];
    const int*   lens  = (const int*)d_in[13];
    float*       out   = (float*)d_out;

    static cudaStream_t sB = nullptr, sC = nullptr;
    static cudaEvent_t e0 = nullptr, eX = nullptr, eV = nullptr,
                       eC = nullptr, eFA0 = nullptr, eFA1 = nullptr;
    if (sB == nullptr) {
        cudaStreamCreateWithFlags(&sB, cudaStreamNonBlocking);
        cudaStreamCreateWithFlags(&sC, cudaStreamNonBlocking);
        cudaEventCreateWithFlags(&e0, cudaEventDisableTiming);
        cudaEventCreateWithFlags(&eX, cudaEventDisableTiming);
        cudaEventCreateWithFlags(&eV, cudaEventDisableTiming);
        cudaEventCreateWithFlags(&eC, cudaEventDisableTiming);
        cudaEventCreateWithFlags(&eFA0, cudaEventDisableTiming);
        cudaEventCreateWithFlags(&eFA1, cudaEventDisableTiming);
        cudaFuncSetAttribute(hgemm_qk,
                             cudaFuncAttributeMaxDynamicSharedMemorySize, HG_BYTES);
        cudaFuncSetAttribute(hgemm_v,
                             cudaFuncAttributeMaxDynamicSharedMemorySize, HG_BYTES);
        cudaFuncSetAttribute(hgemm_o,
                             cudaFuncAttributeMaxDynamicSharedMemorySize, HG_BYTES);
        cudaFuncSetAttribute(flash_attn,
                             cudaFuncAttributeMaxDynamicSharedMemorySize, FA_BYTES);
    }

    const int cgx = (DD * DD) / (256 * 16);   // 1024 blocks per tensor

    // fork side branches off the captured (legacy) stream
    cudaEventRecord(e0, 0);
    cudaStreamWaitEvent(sB, e0, 0);
    cudaStreamWaitEvent(sC, e0, 0);

    // M: wq, wk, x converts
    convert_all<<<dim3(cgx, 3), 256>>>(wq, wk, wv, wo, wq_s, wk_s, wv_s, wo_s,
                                       x, 0, 1, 4);
    cudaEventRecord(eX, 0);   // wq/wk/x converted

    // B: wv convert -> V gemm (after x)
    convert_all<<<dim3(cgx, 1), 256, 0, sB>>>(wq, wk, wv, wo, wq_s, wk_s, wv_s,
                                              wo_s, x, 2, 2, 2);
    cudaStreamWaitEvent(sB, eX, 0);
    hgemm_v<<<dim3(16, 16), 256, HG_BYTES, sB>>>();
    cudaEventRecord(eV, sB);

    // C: wo convert
    convert_all<<<dim3(cgx, 1), 256, 0, sC>>>(wq, wk, wv, wo, wq_s, wk_s, wv_s,
                                              wo_s, x, 3, 3, 3);
    cudaEventRecord(eC, sC);

    // M: full QK -> full norm -> FA_b0 (needs V)
    hgemm_qk<<<dim3(16, 16, 2), 256, HG_BYTES>>>();
    norm_rope<<<dim3(MM, 2), 256>>>(cosT, sinT, qn_w, kn_w);
    cudaStreamWaitEvent(0, eV, 0);
    flash_attn<<<dim3(SS / 64, HH), 128, FA_BYTES>>>(lens, 0);
    cudaEventRecord(eFA0, 0);

    // B: FA_b1 after FA_b0 (overlaps O_b0 on M)
    cudaStreamWaitEvent(sB, eFA0, 0);
    flash_attn<<<dim3(SS / 64, HH), 128, FA_BYTES, sB>>>(lens, 1);
    cudaEventRecord(eFA1, sB);

    // M: O_b0 (needs wo), then O_b1 after FA_b1
    cudaStreamWaitEvent(0, eC, 0);
    hgemm_o<<<dim3(16, 8), 256, HG_BYTES>>>(out, 0);
    cudaStreamWaitEvent(0, eFA1, 0);
    hgemm_o<<<dim3(16, 8), 256, HG_BYTES>>>(out, 1024);
}

// round 15
// speedup vs baseline: 1.1129x; 1.1129x over previous
#include <cuda_runtime.h>
#include <cuda_fp16.h>
#include <cstdint>
#include <stdint.h>
#include <math.h>

using u32 = unsigned int;

// Problem constants
#define BB 2
#define SS 1024
#define DD 2048
#define HH 16
#define DHD 128
#define MM (BB * SS)   // 2048 rows

// ---------------------------------------------------------------------------
// Scratch (__device__ globals; allocation-free per harness rules)
// ---------------------------------------------------------------------------
__device__ __half g_wq[DD * DD];
__device__ __half g_wk[DD * DD];
__device__ __half g_wv[DD * DD];
__device__ __half g_wo[DD * DD];
__device__ __half g_xh[MM * DD];      // hidden_states fp16
__device__ __half g_attnh[MM * DD];   // attention output fp16
__device__ __half g_qh[MM * DD];      // Q (post norm+rope, in place)
__device__ __half g_kh[MM * DD];      // K (post norm+rope, in place)
__device__ __half g_vh[MM * DD];      // V (fp16)

// ---------------------------------------------------------------------------
// PTX helpers
// ---------------------------------------------------------------------------
__device__ __forceinline__ uint4 ldsm_x4(u32 addr) {
    uint4 r;
    asm volatile("ldmatrix.sync.aligned.m8n8.x4.shared.b16 {%0,%1,%2,%3}, [%4];"
                 : "=r"(r.x), "=r"(r.y), "=r"(r.z), "=r"(r.w) : "r"(addr));
    return r;
}
__device__ __forceinline__ uint4 ldsm_x4_t(u32 addr) {
    uint4 r;
    asm volatile("ldmatrix.sync.aligned.m8n8.x4.trans.shared.b16 {%0,%1,%2,%3}, [%4];"
                 : "=r"(r.x), "=r"(r.y), "=r"(r.z), "=r"(r.w) : "r"(addr));
    return r;
}
__device__ __forceinline__ void mma16816(float* c, const uint4& a, u32 b0, u32 b1) {
    asm volatile(
        "mma.sync.aligned.m16n8k16.row.col.f32.f16.f16.f32 "
        "{%0,%1,%2,%3}, {%4,%5,%6,%7}, {%8,%9}, {%0,%1,%2,%3};"
        : "+f"(c[0]), "+f"(c[1]), "+f"(c[2]), "+f"(c[3])
        : "r"(a.x), "r"(a.y), "r"(a.z), "r"(a.w), "r"(b0), "r"(b1));
}
__device__ __forceinline__ void cp16(u32 dst, const void* src) {
    asm volatile("cp.async.cg.shared.global [%0], [%1], 16;" :: "r"(dst), "l"(src));
}
#define CP_COMMIT() asm volatile("cp.async.commit_group;")
#define CP_WAIT(N)  asm volatile("cp.async.wait_group %0;" :: "n"(N))

__device__ __forceinline__ u32 h2u(float a, float b) {
    __half2 h = __floats2half2_rn(a, b);
    return *reinterpret_cast<u32*>(&h);
}
__device__ __forceinline__ u32 ex2_h2(u32 v) {
    asm("ex2.approx.f16x2 %0, %0;" : "+r"(v));
    return v;
}
__device__ __forceinline__ u32 smaddr(const void* p) {
    return (u32)__cvta_generic_to_shared(p);
}

// ---------------------------------------------------------------------------
// Kernel 1: converts. blockIdx.y remapped via m0/m1/m2 params:
//   0..3 -> weights wq/wk/wv/wo, 4 -> hidden_states.
// ---------------------------------------------------------------------------
__global__ __launch_bounds__(256) void convert_all(
    const int* __restrict__ wq, const int* __restrict__ wk,
    const int* __restrict__ wv, const int* __restrict__ wo,
    const float* __restrict__ wq_s, const float* __restrict__ wk_s,
    const float* __restrict__ wv_s, const float* __restrict__ wo_s,
    const float* __restrict__ x, int m0, int m1, int m2) {
    const int y = (blockIdx.y == 0) ? m0 : (blockIdx.y == 1) ? m1 : m2;
    const int i = (blockIdx.x * 256 + threadIdx.x) * 16;
    __align__(16) __half h[16];
    if (y == 4) {
#pragma unroll
        for (int u = 0; u < 4; u++) {
            float4 a = *(const float4*)(x + i + 4 * u);
            h[4 * u + 0] = __float2half(a.x);
            h[4 * u + 1] = __float2half(a.y);
            h[4 * u + 2] = __float2half(a.z);
            h[4 * u + 3] = __float2half(a.w);
        }
        *(uint4*)(g_xh + i)     = *(const uint4*)h;
        *(uint4*)(g_xh + i + 8) = *(const uint4*)(h + 8);
        return;
    }
    const int*   w = (y == 0) ? wq : (y == 1) ? wk : (y == 2) ? wv : wo;
    const float* s = (y == 0) ? wq_s : (y == 1) ? wk_s : (y == 2) ? wv_s : wo_s;
    __half*    out = (y == 0) ? g_wq : (y == 1) ? g_wk : (y == 2) ? g_wv : g_wo;
    float sc = s[i >> 11];
#pragma unroll
    for (int u = 0; u < 4; u++) {
        int4 a = *(const int4*)(w + i + 4 * u);
        h[4 * u + 0] = __float2half((float)a.x * sc);
        h[4 * u + 1] = __float2half((float)a.y * sc);
        h[4 * u + 2] = __float2half((float)a.z * sc);
        h[4 * u + 3] = __float2half((float)a.w * sc);
    }
    *(uint4*)(out + i)     = *(const uint4*)h;
    *(uint4*)(out + i + 8) = *(const uint4*)(h + 8);
}

// ---------------------------------------------------------------------------
// HGEMM core (R6 measured-best): 128x128 tile, BK=64, 3-stage cp.async,
// 256 threads, warp tile 64x32, 2 CTAs/SM.
// ---------------------------------------------------------------------------
#define HG_STG 9216                       // halfs per matrix per stage (128*72)
#define HG_STAGE_BYTES (2 * HG_STG * 2)   // A+B, 36864 B
#define HG_BYTES (3 * HG_STAGE_BYTES)     // 110592 B

template <typename OutT>
__device__ __forceinline__ void store2(OutT* p, float a, float b);
template <> __device__ __forceinline__ void store2<float>(float* p, float a, float b) {
    *(float2*)p = make_float2(a, b);
}
template <> __device__ __forceinline__ void store2<__half>(__half* p, float a, float b) {
    *(__half2*)p = __floats2half2_rn(a, b);
}

template <typename OutT>
__device__ __forceinline__ void hgemm_body(const __half* __restrict__ A,
                                           const __half* __restrict__ B,
                                           OutT* __restrict__ C,
                                           __half* hsm, int bm, int bn) {
    const u32 smb = smaddr(hsm);
    const int t = threadIdx.x, warp = t >> 5, lane = t & 31;
    const int wm = (warp & 1) * 64, wn = (warp >> 1) * 32;
    const int lr = lane & 7, g = lane >> 3;
    const u32 aOff = (u32)(((wm + lr + (g & 1) * 8) * 72 + (g >> 1) * 8) * 2);
    const u32 bOff = (u32)(((wn + lr + (g >> 1) * 8) * 72 + (g & 1) * 8) * 2);

    float c[4][4][4];
#pragma unroll
    for (int mi = 0; mi < 4; mi++)
#pragma unroll
        for (int ni = 0; ni < 4; ni++)
#pragma unroll
            for (int e = 0; e < 4; e++) c[mi][ni][e] = 0.f;

    auto load_stage = [&](int st, int k0) {
        u32 sb = smb + (u32)(st * HG_STAGE_BYTES);
#pragma unroll
        for (int i = 0; i < 4; i++) {
            int id = t + 256 * i;
            int r = id >> 3, cc = id & 7;
            cp16(sb + (u32)((r * 72 + cc * 8) * 2),
                 A + (size_t)(bm + r) * DD + k0 + cc * 8);
            cp16(sb + (u32)(HG_STG * 2) + (u32)((r * 72 + cc * 8) * 2),
                 B + (size_t)(bn + r) * DD + k0 + cc * 8);
        }
    };

    load_stage(0, 0);  CP_COMMIT();
    load_stage(1, 64); CP_COMMIT();

    for (int kt = 0; kt < 32; kt++) {
        if (kt < 31) { CP_WAIT(1); } else { CP_WAIT(0); }
        __syncthreads();
        if (kt + 2 < 32) { load_stage((kt + 2) % 3, (kt + 2) * 64); CP_COMMIT(); }

        u32 ab = smb + (u32)((kt % 3) * HG_STAGE_BYTES) + aOff;
        u32 bb = smb + (u32)((kt % 3) * HG_STAGE_BYTES + HG_STG * 2) + bOff;
#pragma unroll
        for (int ks = 0; ks < 64; ks += 16) {
            uint4 af[4], bf[2];
#pragma unroll
            for (int mi = 0; mi < 4; mi++)
                af[mi] = ldsm_x4(ab + (u32)((mi * 16 * 72 + ks) * 2));
#pragma unroll
            for (int np = 0; np < 2; np++)
                bf[np] = ldsm_x4(bb + (u32)((np * 16 * 72 + ks) * 2));
#pragma unroll
            for (int mi = 0; mi < 4; mi++)
#pragma unroll
                for (int np = 0; np < 2; np++) {
                    mma16816(c[mi][np * 2 + 0], af[mi], bf[np].x, bf[np].y);
                    mma16816(c[mi][np * 2 + 1], af[mi], bf[np].z, bf[np].w);
                }
        }
    }

    const int r0 = bm + wm + (lane >> 2);
    const int cb = bn + wn + (lane & 3) * 2;
#pragma unroll
    for (int mi = 0; mi < 4; mi++)
#pragma unroll
        for (int ni = 0; ni < 4; ni++) {
            int row = r0 + mi * 16, col = cb + ni * 8;
            store2<OutT>(C + (size_t)row * DD + col, c[mi][ni][0], c[mi][ni][1]);
            store2<OutT>(C + (size_t)(row + 8) * DD + col, c[mi][ni][2], c[mi][ni][3]);
        }
}

// Kernel 2a: Q/K GEMM (z selects weight + destination, fp16 out)
__global__ __launch_bounds__(256, 2) void hgemm_qk() {
    extern __shared__ __half hsm[];
    const int z = blockIdx.z;
    const __half* B = (z == 0) ? g_wq : g_wk;
    __half*       C = (z == 0) ? g_qh : g_kh;
    hgemm_body<__half>(g_xh, B, C, hsm, blockIdx.y * 128, blockIdx.x * 128);
}

// Kernel 2b: V GEMM (fp16 out; runs on side stream)
__global__ __launch_bounds__(256, 2) void hgemm_v() {
    extern __shared__ __half hsm[];
    hgemm_body<__half>(g_xh, g_wv, g_vh, hsm, blockIdx.y * 128, blockIdx.x * 128);
}

// Kernel 2c: O-projection GEMM (fp32 out to harness buffer)
__global__ __launch_bounds__(256, 2) void hgemm_o(float* __restrict__ C) {
    extern __shared__ __half hsm[];
    hgemm_body<float>(g_attnh, g_wo, C, hsm, blockIdx.y * 128, blockIdx.x * 128);
}

// ---------------------------------------------------------------------------
// Kernel 3: RMSNorm + RoPE, fp16 in/out, in place on g_qh / g_kh.
// ---------------------------------------------------------------------------
__global__ __launch_bounds__(256) void norm_rope(const float* __restrict__ cosT,
                                                 const float* __restrict__ sinT,
                                                 const float* __restrict__ qn_w,
                                                 const float* __restrict__ kn_w) {
    __half* x       = (blockIdx.y == 0) ? g_qh : g_kh;
    const float* w  = (blockIdx.y == 0) ? qn_w : kn_w;
    const int row = blockIdx.x;
    const int s   = row & (SS - 1);
    const int t   = threadIdx.x;

    __shared__ float buf[DD];
    __shared__ float red[8];

    __half* xr = x + (size_t)row * DD;
    float ss = 0.f;
    {
        int i = t * 8;
        uint4 raw = *(const uint4*)(xr + i);
        const __half* hp = (const __half*)&raw;
#pragma unroll
        for (int j = 0; j < 8; j++) {
            float v = __half2float(hp[j]);
            buf[i + j] = v;
            ss += v * v;
        }
    }
#pragma unroll
    for (int off = 16; off; off >>= 1) ss += __shfl_xor_sync(0xffffffffu, ss, off);
    if ((t & 31) == 0) red[t >> 5] = ss;
    __syncthreads();
    float tot = 0.f;
#pragma unroll
    for (int wI = 0; wI < 8; wI++) tot += red[wI];
    const float inv = rsqrtf(tot * (1.0f / DD) + 1e-6f);

#pragma unroll
    for (int u = 0; u < 4; u++) {
        int p  = t + u * 256;
        int hh = p >> 6;
        int i  = p & 63;
        int d1 = hh * DHD + i;
        int d2 = d1 + 64;
        float y1 = buf[d1] * inv * w[d1];
        float y2 = buf[d2] * inv * w[d2];
        float c1 = cosT[s * DHD + i],      s1 = sinT[s * DHD + i];
        float c2 = cosT[s * DHD + 64 + i], s2 = sinT[s * DHD + 64 + i];
        xr[d1] = __float2half(y1 * c1 - y2 * s1);
        xr[d2] = __float2half(y2 * c2 + y1 * s2);
    }
}

// ---------------------------------------------------------------------------
// Kernel 4: flash-attention (R11): S-prefetch pipeline, fp16x2 ex2 softmax,
// mma row-sums. K 3-slot ring, V 2-slot ring, 96 KB smem, 128 threads.
// ---------------------------------------------------------------------------
#define FA_TILE_HALFS (64 * 128)                 // 8192
#define FA_KOFF FA_TILE_HALFS                    // after Q
#define FA_VOFF (FA_TILE_HALFS * 4)              // after Q + 3 K slots
#define FA_BYTES (FA_TILE_HALFS * 6 * 2)         // 98304

__device__ __forceinline__ void fa_load_tile(u32 base, const __half* src,
                                             int kt, int t) {
#pragma unroll
    for (int i = 0; i < 8; i++) {
        int id = t + 128 * i;
        int r = id >> 4, cc = id & 15;
        u32 off = (u32)(((r * 128) + ((cc ^ (r & 7)) << 3)) << 1);
        cp16(base + off, src + (size_t)(kt * 64 + r) * DD + cc * 8);
    }
}

__global__ __launch_bounds__(128) void flash_attn(const int* __restrict__ lengths) {
    extern __shared__ __half fsm[];
    const u32 smb = smaddr(fsm);

    const int qt = blockIdx.x, h = blockIdx.y, b = blockIdx.z;
    const int t = threadIdx.x, warp = t >> 5, lane = t & 31;
    const int lr = lane & 7, g = lane >> 3;
    const int len = lengths[b];
    const int s0  = qt * 64;
    const int nkt = (len + 63) >> 6;

    const __half* qg = g_qh + (size_t)(b * SS) * DD + h * DHD;
    const __half* kg = g_kh + (size_t)(b * SS) * DD + h * DHD;
    const __half* vg = g_vh + (size_t)(b * SS) * DD + h * DHD;

    // prologue: group A = {Q, K0, V0, K1}, group B = {V1}
#pragma unroll
    for (int i = 0; i < 8; i++) {
        int id = t + 128 * i;
        int r = id >> 4, cc = id & 15;
        u32 off = (u32)(((r * 128) + ((cc ^ (r & 7)) << 3)) << 1);
        cp16(smb + off, qg + (size_t)(s0 + r) * DD + cc * 8);
    }
    fa_load_tile(smb + (u32)(FA_KOFF * 2), kg, 0, t);
    fa_load_tile(smb + (u32)(FA_VOFF * 2), vg, 0, t);
    if (nkt > 1) fa_load_tile(smb + (u32)((FA_KOFF + FA_TILE_HALFS) * 2), kg, 1, t);
    CP_COMMIT();
    if (nkt > 1) {
        fa_load_tile(smb + (u32)((FA_VOFF + FA_TILE_HALFS) * 2), vg, 1, t);
        CP_COMMIT();
    }

    const int qrow = 16 * warp + lr + (g & 1) * 8, qx = qrow & 7;
    const int krow = lr + (g >> 1) * 8, kcol = g & 1, kx = krow & 7;
    const int vrow = lr + (g & 1) * 8, vcol = g >> 1, vx = vrow & 7;

    CP_WAIT(1);
    __syncthreads();

    uint4 qf[8];
#pragma unroll
    for (int ks = 0; ks < 8; ks++)
        qf[ks] = ldsm_x4(smb + (u32)(((qrow * 128) +
                          (((2 * ks + (g >> 1)) ^ qx) << 3)) << 1));

    auto compute_S = [&](int kt, float (*s)[4]) {
        const u32 kbase = smb + (u32)((FA_KOFF + (kt % 3) * FA_TILE_HALFS) * 2);
#pragma unroll
        for (int j = 0; j < 8; j++)
#pragma unroll
            for (int e = 0; e < 4; e++) s[j][e] = 0.f;
#pragma unroll
        for (int ks = 0; ks < 8; ks++) {
#pragma unroll
            for (int np = 0; np < 4; np++) {
                uint4 bf = ldsm_x4(kbase + (u32)((((16 * np + krow) * 128) +
                                    (((2 * ks + kcol) ^ kx) << 3)) << 1));
                mma16816(s[2 * np],     qf[ks], bf.x, bf.y);
                mma16816(s[2 * np + 1], qf[ks], bf.z, bf.w);
            }
        }
    };

    float o[16][4];
#pragma unroll
    for (int j2 = 0; j2 < 16; j2++)
#pragma unroll
        for (int e = 0; e < 4; e++) o[j2][e] = 0.f;
    float m0 = -1e30f, m1 = -1e30f, l0 = 0.f, l1 = 0.f;
    const float scl = 0.12751784766914164f;   // log2(e)/sqrt(128)
    const u32 ONES2 = 0x3C003C00u;            // half2(1.0, 1.0)

    float s_cur[8][4], s_next[8][4];
    compute_S(0, s_cur);

    for (int kt = 0; kt < nkt; kt++) {
        CP_WAIT(1);
        __syncthreads();
        if (kt + 2 < nkt) {
            fa_load_tile(smb + (u32)((FA_KOFF + ((kt + 2) % 3) * FA_TILE_HALFS) * 2),
                         kg, kt + 2, t);
            CP_COMMIT();
        }
        if (kt + 1 < nkt) compute_S(kt + 1, s_next);

        // ---- mask + online softmax on s_cur (base-2, fp16x2 ex2) ----
        const int cb = kt * 64 + 2 * (lane & 3);
        float mx0 = -1e30f, mx1 = -1e30f;
#pragma unroll
        for (int j = 0; j < 8; j++) {
            int c0 = cb + 8 * j;
            s_cur[j][0] = (c0 < len)     ? s_cur[j][0] * scl : -1e30f;
            s_cur[j][1] = (c0 + 1 < len) ? s_cur[j][1] * scl : -1e30f;
            s_cur[j][2] = (c0 < len)     ? s_cur[j][2] * scl : -1e30f;
            s_cur[j][3] = (c0 + 1 < len) ? s_cur[j][3] * scl : -1e30f;
            mx0 = fmaxf(mx0, fmaxf(s_cur[j][0], s_cur[j][1]));
            mx1 = fmaxf(mx1, fmaxf(s_cur[j][2], s_cur[j][3]));
        }
        mx0 = fmaxf(mx0, __shfl_xor_sync(0xffffffffu, mx0, 1));
        mx0 = fmaxf(mx0, __shfl_xor_sync(0xffffffffu, mx0, 2));
        mx1 = fmaxf(mx1, __shfl_xor_sync(0xffffffffu, mx1, 1));
        mx1 = fmaxf(mx1, __shfl_xor_sync(0xffffffffu, mx1, 2));

        float mn0 = fmaxf(m0, mx0), mn1 = fmaxf(m1, mx1);
        float al0 = exp2f(m0 - mn0), al1 = exp2f(m1 - mn1);

        u32 pf[8][2];
#pragma unroll
        for (int j = 0; j < 8; j++) {
            pf[j][0] = ex2_h2(h2u(s_cur[j][0] - mn0, s_cur[j][1] - mn0));
            pf[j][1] = ex2_h2(h2u(s_cur[j][2] - mn1, s_cur[j][3] - mn1));
        }

        // row sums of P via tensor core (B = ones)
        float lacc[4] = {0.f, 0.f, 0.f, 0.f};
#pragma unroll
        for (int k2 = 0; k2 < 4; k2++) {
            uint4 a;
            a.x = pf[2 * k2][0];     a.y = pf[2 * k2][1];
            a.z = pf[2 * k2 + 1][0]; a.w = pf[2 * k2 + 1][1];
            mma16816(lacc, a, ONES2, ONES2);
        }
        l0 = l0 * al0 + lacc[0];
        l1 = l1 * al1 + lacc[2];
        m0 = mn0; m1 = mn1;
#pragma unroll
        for (int j2 = 0; j2 < 16; j2++) {
            o[j2][0] *= al0; o[j2][1] *= al0;
            o[j2][2] *= al1; o[j2][3] *= al1;
        }

        // ---- O += P V (V slot kt&1) ----
        const u32 vbase = smb + (u32)((FA_VOFF + (kt & 1) * FA_TILE_HALFS) * 2);
#pragma unroll
        for (int k2 = 0; k2 < 4; k2++) {
            uint4 a;
            a.x = pf[2 * k2][0];     a.y = pf[2 * k2][1];
            a.z = pf[2 * k2 + 1][0]; a.w = pf[2 * k2 + 1][1];
#pragma unroll
            for (int np = 0; np < 8; np++) {
                uint4 bf = ldsm_x4_t(vbase + (u32)((((16 * k2 + vrow) * 128) +
                                     (((2 * np + vcol) ^ vx) << 3)) << 1));
                mma16816(o[2 * np],     a, bf.x, bf.y);
                mma16816(o[2 * np + 1], a, bf.z, bf.w);
            }
        }

        __syncthreads();    // all PV reads of V slot kt&1 done
        if (kt + 2 < nkt) {
            fa_load_tile(smb + (u32)((FA_VOFF + (kt & 1) * FA_TILE_HALFS) * 2),
                         vg, kt + 2, t);
            CP_COMMIT();
        }
        if (kt + 1 < nkt) {
#pragma unroll
            for (int j = 0; j < 8; j++)
#pragma unroll
                for (int e = 0; e < 4; e++) s_cur[j][e] = s_next[j][e];
        }
    }

    const float il0 = 1.f / l0, il1 = 1.f / l1;
    const int r0 = s0 + 16 * warp + (lane >> 2);
    __half* ob = g_attnh + (size_t)(b * SS) * DD + h * DHD;
#pragma unroll
    for (int j2 = 0; j2 < 16; j2++) {
        int col = 8 * j2 + 2 * (lane & 3);
        *(__half2*)(ob + (size_t)r0 * DD + col) =
            __floats2half2_rn(o[j2][0] * il0, o[j2][1] * il0);
        *(__half2*)(ob + (size_t)(r0 + 8) * DD + col) =
            __floats2half2_rn(o[j2][2] * il1, o[j2][3] * il1);
    }
}

// ---------------------------------------------------------------------------
// Launch: R12 graph (measured best).
//   M (stream 0): conv(wq,wk,x) -> QK gemm -> norm -> [eB] FA -> [eC] O gemm
//   B:            conv(wv) -> [eX] V gemm -> eB
//   C:            conv(wo) -> eC
// ---------------------------------------------------------------------------
extern "C" void kernel_launch(void* const* d_in, const int* in_sizes, int n_in,
                              void* d_out, int out_size) {
    const float* x     = (const float*)d_in[0];
    const float* wq_s  = (const float*)d_in[1];
    const float* wk_s  = (const float*)d_in[2];
    const float* wv_s  = (const float*)d_in[3];
    const float* wo_s  = (const float*)d_in[4];
    const float* qn_w  = (const float*)d_in[5];
    const float* kn_w  = (const float*)d_in[6];
    const float* cosT  = (const float*)d_in[7];
    const float* sinT  = (const float*)d_in[8];
    const int*   wq    = (const int*)d_in[9];
    const int*   wk    = (const int*)d_in[10];
    const int*   wv    = (const int*)d_in[11];
    const int*   wo    = (const int*)d_in[12];
    const int*   lens  = (const int*)d_in[13];
    float*       out   = (float*)d_out;

    static cudaStream_t sB = nullptr, sC = nullptr;
    static cudaEvent_t e0 = nullptr, eX = nullptr, eB = nullptr, eC = nullptr;
    if (sB == nullptr) {
        cudaStreamCreateWithFlags(&sB, cudaStreamNonBlocking);
        cudaStreamCreateWithFlags(&sC, cudaStreamNonBlocking);
        cudaEventCreateWithFlags(&e0, cudaEventDisableTiming);
        cudaEventCreateWithFlags(&eX, cudaEventDisableTiming);
        cudaEventCreateWithFlags(&eB, cudaEventDisableTiming);
        cudaEventCreateWithFlags(&eC, cudaEventDisableTiming);
        cudaFuncSetAttribute(hgemm_qk,
                             cudaFuncAttributeMaxDynamicSharedMemorySize, HG_BYTES);
        cudaFuncSetAttribute(hgemm_v,
                             cudaFuncAttributeMaxDynamicSharedMemorySize, HG_BYTES);
        cudaFuncSetAttribute(hgemm_o,
                             cudaFuncAttributeMaxDynamicSharedMemorySize, HG_BYTES);
        cudaFuncSetAttribute(flash_attn,
                             cudaFuncAttributeMaxDynamicSharedMemorySize, FA_BYTES);
    }

    const int cgx = (DD * DD) / (256 * 16);   // 1024 blocks per tensor

    // fork side branches off the captured (legacy) stream
    cudaEventRecord(e0, 0);
    cudaStreamWaitEvent(sB, e0, 0);
    cudaStreamWaitEvent(sC, e0, 0);

    // M: wq, wk, x converts
    convert_all<<<dim3(cgx, 3), 256>>>(wq, wk, wv, wo, wq_s, wk_s, wv_s, wo_s,
                                       x, 0, 1, 4);
    cudaEventRecord(eX, 0);   // wq/wk/x converted

    // B: wv convert, then V gemm (after x ready)
    convert_all<<<dim3(cgx, 1), 256, 0, sB>>>(wq, wk, wv, wo, wq_s, wk_s, wv_s,
                                              wo_s, x, 2, 2, 2);
    cudaStreamWaitEvent(sB, eX, 0);
    hgemm_v<<<dim3(16, 16), 256, HG_BYTES, sB>>>();
    cudaEventRecord(eB, sB);

    // C: wo convert
    convert_all<<<dim3(cgx, 1), 256, 0, sC>>>(wq, wk, wv, wo, wq_s, wk_s, wv_s,
                                              wo_s, x, 3, 3, 3);
    cudaEventRecord(eC, sC);

    // M: QK gemm -> norm+rope
    hgemm_qk<<<dim3(16, 16, 2), 256, HG_BYTES>>>();
    norm_rope<<<dim3(MM, 2), 256>>>(cosT, sinT, qn_w, kn_w);

    // M: FA needs V (eB)
    cudaStreamWaitEvent(0, eB, 0);
    flash_attn<<<dim3(SS / 64, HH, BB), 128, FA_BYTES>>>(lens);

    // M: O gemm needs wo (eC)
    cudaStreamWaitEvent(0, eC, 0);
    hgemm_o<<<dim3(16, 16), 256, HG_BYTES>>>(out);
}

// round 16
// speedup vs baseline: 1.2046x; 1.0824x over previous
#include <cuda_runtime.h>
#include <cuda_fp16.h>
#include <cstdint>
#include <stdint.h>
#include <math.h>

using u32 = unsigned int;

// Problem constants
#define BB 2
#define SS 1024
#define DD 2048
#define HH 16
#define DHD 128
#define MM (BB * SS)   // 2048 rows

// ---------------------------------------------------------------------------
// Scratch (__device__ globals; allocation-free per harness rules)
// ---------------------------------------------------------------------------
__device__ __half g_wq[DD * DD];
__device__ __half g_wk[DD * DD];
__device__ __half g_wv[DD * DD];
__device__ __half g_wo[DD * DD];
__device__ __half g_xh[MM * DD];      // hidden_states fp16
__device__ __half g_attnh[MM * DD];   // attention output fp16
__device__ __half g_qh[MM * DD];      // Q (post norm+rope, in place)
__device__ __half g_kh[MM * DD];      // K (post norm+rope, in place)
__device__ __half g_vh[MM * DD];      // V (fp16)

// ---------------------------------------------------------------------------
// PTX helpers
// ---------------------------------------------------------------------------
__device__ __forceinline__ uint4 ldsm_x4(u32 addr) {
    uint4 r;
    asm volatile("ldmatrix.sync.aligned.m8n8.x4.shared.b16 {%0,%1,%2,%3}, [%4];"
                 : "=r"(r.x), "=r"(r.y), "=r"(r.z), "=r"(r.w) : "r"(addr));
    return r;
}
__device__ __forceinline__ uint4 ldsm_x4_t(u32 addr) {
    uint4 r;
    asm volatile("ldmatrix.sync.aligned.m8n8.x4.trans.shared.b16 {%0,%1,%2,%3}, [%4];"
                 : "=r"(r.x), "=r"(r.y), "=r"(r.z), "=r"(r.w) : "r"(addr));
    return r;
}
__device__ __forceinline__ void mma16816(float* c, const uint4& a, u32 b0, u32 b1) {
    asm volatile(
        "mma.sync.aligned.m16n8k16.row.col.f32.f16.f16.f32 "
        "{%0,%1,%2,%3}, {%4,%5,%6,%7}, {%8,%9}, {%0,%1,%2,%3};"
        : "+f"(c[0]), "+f"(c[1]), "+f"(c[2]), "+f"(c[3])
        : "r"(a.x), "r"(a.y), "r"(a.z), "r"(a.w), "r"(b0), "r"(b1));
}
__device__ __forceinline__ void cp16(u32 dst, const void* src) {
    asm volatile("cp.async.cg.shared.global [%0], [%1], 16;" :: "r"(dst), "l"(src));
}
#define CP_COMMIT() asm volatile("cp.async.commit_group;")
#define CP_WAIT(N)  asm volatile("cp.async.wait_group %0;" :: "n"(N))

__device__ __forceinline__ u32 h2u(float a, float b) {
    __half2 h = __floats2half2_rn(a, b);
    return *reinterpret_cast<u32*>(&h);
}
__device__ __forceinline__ u32 ex2_h2(u32 v) {
    asm("ex2.approx.f16x2 %0, %0;" : "+r"(v));
    return v;
}
__device__ __forceinline__ u32 smaddr(const void* p) {
    return (u32)__cvta_generic_to_shared(p);
}

// rows [r0, r0+128) of a K/V-style tensor are dead iff the whole block lies
// at sequence positions >= len of its batch (block never crosses a batch).
__device__ __forceinline__ bool kv_block_dead(int r0, const int* lens) {
    int b = r0 >> 10;          // batch (SS = 1024)
    int s = r0 & (SS - 1);
    return s >= lens[b];
}

// ---------------------------------------------------------------------------
// Kernel 1: converts. blockIdx.y remapped via m0/m1/m2 params:
//   0..3 -> weights wq/wk/wv/wo, 4 -> hidden_states.
// ---------------------------------------------------------------------------
__global__ __launch_bounds__(256) void convert_all(
    const int* __restrict__ wq, const int* __restrict__ wk,
    const int* __restrict__ wv, const int* __restrict__ wo,
    const float* __restrict__ wq_s, const float* __restrict__ wk_s,
    const float* __restrict__ wv_s, const float* __restrict__ wo_s,
    const float* __restrict__ x, int m0, int m1, int m2) {
    const int y = (blockIdx.y == 0) ? m0 : (blockIdx.y == 1) ? m1 : m2;
    const int i = (blockIdx.x * 256 + threadIdx.x) * 16;
    __align__(16) __half h[16];
    if (y == 4) {
#pragma unroll
        for (int u = 0; u < 4; u++) {
            float4 a = *(const float4*)(x + i + 4 * u);
            h[4 * u + 0] = __float2half(a.x);
            h[4 * u + 1] = __float2half(a.y);
            h[4 * u + 2] = __float2half(a.z);
            h[4 * u + 3] = __float2half(a.w);
        }
        *(uint4*)(g_xh + i)     = *(const uint4*)h;
        *(uint4*)(g_xh + i + 8) = *(const uint4*)(h + 8);
        return;
    }
    const int*   w = (y == 0) ? wq : (y == 1) ? wk : (y == 2) ? wv : wo;
    const float* s = (y == 0) ? wq_s : (y == 1) ? wk_s : (y == 2) ? wv_s : wo_s;
    __half*    out = (y == 0) ? g_wq : (y == 1) ? g_wk : (y == 2) ? g_wv : g_wo;
    float sc = s[i >> 11];
#pragma unroll
    for (int u = 0; u < 4; u++) {
        int4 a = *(const int4*)(w + i + 4 * u);
        h[4 * u + 0] = __float2half((float)a.x * sc);
        h[4 * u + 1] = __float2half((float)a.y * sc);
        h[4 * u + 2] = __float2half((float)a.z * sc);
        h[4 * u + 3] = __float2half((float)a.w * sc);
    }
    *(uint4*)(out + i)     = *(const uint4*)h;
    *(uint4*)(out + i + 8) = *(const uint4*)(h + 8);
}

// ---------------------------------------------------------------------------
// HGEMM core (R6 measured-best): 128x128 tile, BK=64, 3-stage cp.async,
// 256 threads, warp tile 64x32, 2 CTAs/SM.
// ---------------------------------------------------------------------------
#define HG_STG 9216                       // halfs per matrix per stage (128*72)
#define HG_STAGE_BYTES (2 * HG_STG * 2)   // A+B, 36864 B
#define HG_BYTES (3 * HG_STAGE_BYTES)     // 110592 B

template <typename OutT>
__device__ __forceinline__ void store2(OutT* p, float a, float b);
template <> __device__ __forceinline__ void store2<float>(float* p, float a, float b) {
    *(float2*)p = make_float2(a, b);
}
template <> __device__ __forceinline__ void store2<__half>(__half* p, float a, float b) {
    *(__half2*)p = __floats2half2_rn(a, b);
}

template <typename OutT>
__device__ __forceinline__ void hgemm_body(const __half* __restrict__ A,
                                           const __half* __restrict__ B,
                                           OutT* __restrict__ C,
                                           __half* hsm, int bm, int bn) {
    const u32 smb = smaddr(hsm);
    const int t = threadIdx.x, warp = t >> 5, lane = t & 31;
    const int wm = (warp & 1) * 64, wn = (warp >> 1) * 32;
    const int lr = lane & 7, g = lane >> 3;
    const u32 aOff = (u32)(((wm + lr + (g & 1) * 8) * 72 + (g >> 1) * 8) * 2);
    const u32 bOff = (u32)(((wn + lr + (g >> 1) * 8) * 72 + (g & 1) * 8) * 2);

    float c[4][4][4];
#pragma unroll
    for (int mi = 0; mi < 4; mi++)
#pragma unroll
        for (int ni = 0; ni < 4; ni++)
#pragma unroll
            for (int e = 0; e < 4; e++) c[mi][ni][e] = 0.f;

    auto load_stage = [&](int st, int k0) {
        u32 sb = smb + (u32)(st * HG_STAGE_BYTES);
#pragma unroll
        for (int i = 0; i < 4; i++) {
            int id = t + 256 * i;
            int r = id >> 3, cc = id & 7;
            cp16(sb + (u32)((r * 72 + cc * 8) * 2),
                 A + (size_t)(bm + r) * DD + k0 + cc * 8);
            cp16(sb + (u32)(HG_STG * 2) + (u32)((r * 72 + cc * 8) * 2),
                 B + (size_t)(bn + r) * DD + k0 + cc * 8);
        }
    };

    load_stage(0, 0);  CP_COMMIT();
    load_stage(1, 64); CP_COMMIT();

    for (int kt = 0; kt < 32; kt++) {
        if (kt < 31) { CP_WAIT(1); } else { CP_WAIT(0); }
        __syncthreads();
        if (kt + 2 < 32) { load_stage((kt + 2) % 3, (kt + 2) * 64); CP_COMMIT(); }

        u32 ab = smb + (u32)((kt % 3) * HG_STAGE_BYTES) + aOff;
        u32 bb = smb + (u32)((kt % 3) * HG_STAGE_BYTES + HG_STG * 2) + bOff;
#pragma unroll
        for (int ks = 0; ks < 64; ks += 16) {
            uint4 af[4], bf[2];
#pragma unroll
            for (int mi = 0; mi < 4; mi++)
                af[mi] = ldsm_x4(ab + (u32)((mi * 16 * 72 + ks) * 2));
#pragma unroll
            for (int np = 0; np < 2; np++)
                bf[np] = ldsm_x4(bb + (u32)((np * 16 * 72 + ks) * 2));
#pragma unroll
            for (int mi = 0; mi < 4; mi++)
#pragma unroll
                for (int np = 0; np < 2; np++) {
                    mma16816(c[mi][np * 2 + 0], af[mi], bf[np].x, bf[np].y);
                    mma16816(c[mi][np * 2 + 1], af[mi], bf[np].z, bf[np].w);
                }
        }
    }

    const int r0 = bm + wm + (lane >> 2);
    const int cb = bn + wn + (lane & 3) * 2;
#pragma unroll
    for (int mi = 0; mi < 4; mi++)
#pragma unroll
        for (int ni = 0; ni < 4; ni++) {
            int row = r0 + mi * 16, col = cb + ni * 8;
            store2<OutT>(C + (size_t)row * DD + col, c[mi][ni][0], c[mi][ni][1]);
            store2<OutT>(C + (size_t)(row + 8) * DD + col, c[mi][ni][2], c[mi][ni][3]);
        }
}

// Kernel 2a: Q/K GEMM (z: 0=Q, 1=K; fp16 out). K blocks beyond len are dead.
__global__ __launch_bounds__(256, 2) void hgemm_qk(const int* __restrict__ lens) {
    extern __shared__ __half hsm[];
    const int z = blockIdx.z;
    const int bm = blockIdx.y * 128;
    if (z == 1 && kv_block_dead(bm, lens)) return;   // K rows never read by FA
    const __half* B = (z == 0) ? g_wq : g_wk;
    __half*       C = (z == 0) ? g_qh : g_kh;
    hgemm_body<__half>(g_xh, B, C, hsm, bm, blockIdx.x * 128);
}

// Kernel 2b: V GEMM (fp16 out). V blocks beyond len are dead.
__global__ __launch_bounds__(256, 2) void hgemm_v(const int* __restrict__ lens) {
    extern __shared__ __half hsm[];
    const int bm = blockIdx.y * 128;
    if (kv_block_dead(bm, lens)) return;             // V rows never read by FA
    hgemm_body<__half>(g_xh, g_wv, g_vh, hsm, bm, blockIdx.x * 128);
}

// Kernel 2c: O-projection GEMM (fp32 out to harness buffer)
__global__ __launch_bounds__(256, 2) void hgemm_o(float* __restrict__ C) {
    extern __shared__ __half hsm[];
    hgemm_body<float>(g_attnh, g_wo, C, hsm, blockIdx.y * 128, blockIdx.x * 128);
}

// ---------------------------------------------------------------------------
// Kernel 3: RMSNorm + RoPE, fp16 in/out, in place on g_qh / g_kh.
// K rows beyond len are dead (never read by FA).
// ---------------------------------------------------------------------------
__global__ __launch_bounds__(256) void norm_rope(const float* __restrict__ cosT,
                                                 const float* __restrict__ sinT,
                                                 const float* __restrict__ qn_w,
                                                 const float* __restrict__ kn_w,
                                                 const int* __restrict__ lens) {
    const int row = blockIdx.x;
    const int s   = row & (SS - 1);
    if (blockIdx.y == 1 && s >= lens[row >> 10]) return;   // dead K row
    __half* x       = (blockIdx.y == 0) ? g_qh : g_kh;
    const float* w  = (blockIdx.y == 0) ? qn_w : kn_w;
    const int t   = threadIdx.x;

    __shared__ float buf[DD];
    __shared__ float red[8];

    __half* xr = x + (size_t)row * DD;
    float ss = 0.f;
    {
        int i = t * 8;
        uint4 raw = *(const uint4*)(xr + i);
        const __half* hp = (const __half*)&raw;
#pragma unroll
        for (int j = 0; j < 8; j++) {
            float v = __half2float(hp[j]);
            buf[i + j] = v;
            ss += v * v;
        }
    }
#pragma unroll
    for (int off = 16; off; off >>= 1) ss += __shfl_xor_sync(0xffffffffu, ss, off);
    if ((t & 31) == 0) red[t >> 5] = ss;
    __syncthreads();
    float tot = 0.f;
#pragma unroll
    for (int wI = 0; wI < 8; wI++) tot += red[wI];
    const float inv = rsqrtf(tot * (1.0f / DD) + 1e-6f);

#pragma unroll
    for (int u = 0; u < 4; u++) {
        int p  = t + u * 256;
        int hh = p >> 6;
        int i  = p & 63;
        int d1 = hh * DHD + i;
        int d2 = d1 + 64;
        float y1 = buf[d1] * inv * w[d1];
        float y2 = buf[d2] * inv * w[d2];
        float c1 = cosT[s * DHD + i],      s1 = sinT[s * DHD + i];
        float c2 = cosT[s * DHD + 64 + i], s2 = sinT[s * DHD + 64 + i];
        xr[d1] = __float2half(y1 * c1 - y2 * s1);
        xr[d2] = __float2half(y2 * c2 + y1 * s2);
    }
}

// ---------------------------------------------------------------------------
// Kernel 4: flash-attention (R11): S-prefetch pipeline, fp16x2 ex2 softmax,
// mma row-sums. K 3-slot ring, V 2-slot ring, 96 KB smem, 128 threads.
// ---------------------------------------------------------------------------
#define FA_TILE_HALFS (64 * 128)                 // 8192
#define FA_KOFF FA_TILE_HALFS                    // after Q
#define FA_VOFF (FA_TILE_HALFS * 4)              // after Q + 3 K slots
#define FA_BYTES (FA_TILE_HALFS * 6 * 2)         // 98304

__device__ __forceinline__ void fa_load_tile(u32 base, const __half* src,
                                             int kt, int t) {
#pragma unroll
    for (int i = 0; i < 8; i++) {
        int id = t + 128 * i;
        int r = id >> 4, cc = id & 15;
        u32 off = (u32)(((r * 128) + ((cc ^ (r & 7)) << 3)) << 1);
        cp16(base + off, src + (size_t)(kt * 64 + r) * DD + cc * 8);
    }
}

__global__ __launch_bounds__(128) void flash_attn(const int* __restrict__ lengths) {
    extern __shared__ __half fsm[];
    const u32 smb = smaddr(fsm);

    const int qt = blockIdx.x, h = blockIdx.y, b = blockIdx.z;
    const int t = threadIdx.x, warp = t >> 5, lane = t & 31;
    const int lr = lane & 7, g = lane >> 3;
    const int len = lengths[b];
    const int s0  = qt * 64;
    const int nkt = (len + 63) >> 6;

    const __half* qg = g_qh + (size_t)(b * SS) * DD + h * DHD;
    const __half* kg = g_kh + (size_t)(b * SS) * DD + h * DHD;
    const __half* vg = g_vh + (size_t)(b * SS) * DD + h * DHD;

    // prologue: group A = {Q, K0, V0, K1}, group B = {V1}
#pragma unroll
    for (int i = 0; i < 8; i++) {
        int id = t + 128 * i;
        int r = id >> 4, cc = id & 15;
        u32 off = (u32)(((r * 128) + ((cc ^ (r & 7)) << 3)) << 1);
        cp16(smb + off, qg + (size_t)(s0 + r) * DD + cc * 8);
    }
    fa_load_tile(smb + (u32)(FA_KOFF * 2), kg, 0, t);
    fa_load_tile(smb + (u32)(FA_VOFF * 2), vg, 0, t);
    if (nkt > 1) fa_load_tile(smb + (u32)((FA_KOFF + FA_TILE_HALFS) * 2), kg, 1, t);
    CP_COMMIT();
    if (nkt > 1) {
        fa_load_tile(smb + (u32)((FA_VOFF + FA_TILE_HALFS) * 2), vg, 1, t);
        CP_COMMIT();
    }

    const int qrow = 16 * warp + lr + (g & 1) * 8, qx = qrow & 7;
    const int krow = lr + (g >> 1) * 8, kcol = g & 1, kx = krow & 7;
    const int vrow = lr + (g & 1) * 8, vcol = g >> 1, vx = vrow & 7;

    CP_WAIT(1);
    __syncthreads();

    uint4 qf[8];
#pragma unroll
    for (int ks = 0; ks < 8; ks++)
        qf[ks] = ldsm_x4(smb + (u32)(((qrow * 128) +
                          (((2 * ks + (g >> 1)) ^ qx) << 3)) << 1));

    auto compute_S = [&](int kt, float (*s)[4]) {
        const u32 kbase = smb + (u32)((FA_KOFF + (kt % 3) * FA_TILE_HALFS) * 2);
#pragma unroll
        for (int j = 0; j < 8; j++)
#pragma unroll
            for (int e = 0; e < 4; e++) s[j][e] = 0.f;
#pragma unroll
        for (int ks = 0; ks < 8; ks++) {
#pragma unroll
            for (int np = 0; np < 4; np++) {
                uint4 bf = ldsm_x4(kbase + (u32)((((16 * np + krow) * 128) +
                                    (((2 * ks + kcol) ^ kx) << 3)) << 1));
                mma16816(s[2 * np],     qf[ks], bf.x, bf.y);
                mma16816(s[2 * np + 1], qf[ks], bf.z, bf.w);
            }
        }
    };

    float o[16][4];
#pragma unroll
    for (int j2 = 0; j2 < 16; j2++)
#pragma unroll
        for (int e = 0; e < 4; e++) o[j2][e] = 0.f;
    float m0 = -1e30f, m1 = -1e30f, l0 = 0.f, l1 = 0.f;
    const float scl = 0.12751784766914164f;   // log2(e)/sqrt(128)
    const u32 ONES2 = 0x3C003C00u;            // half2(1.0, 1.0)

    float s_cur[8][4], s_next[8][4];
    compute_S(0, s_cur);

    for (int kt = 0; kt < nkt; kt++) {
        CP_WAIT(1);
        __syncthreads();
        if (kt + 2 < nkt) {
            fa_load_tile(smb + (u32)((FA_KOFF + ((kt + 2) % 3) * FA_TILE_HALFS) * 2),
                         kg, kt + 2, t);
            CP_COMMIT();
        }
        if (kt + 1 < nkt) compute_S(kt + 1, s_next);

        // ---- mask + online softmax on s_cur (base-2, fp16x2 ex2) ----
        const int cb = kt * 64 + 2 * (lane & 3);
        float mx0 = -1e30f, mx1 = -1e30f;
#pragma unroll
        for (int j = 0; j < 8; j++) {
            int c0 = cb + 8 * j;
            s_cur[j][0] = (c0 < len)     ? s_cur[j][0] * scl : -1e30f;
            s_cur[j][1] = (c0 + 1 < len) ? s_cur[j][1] * scl : -1e30f;
            s_cur[j][2] = (c0 < len)     ? s_cur[j][2] * scl : -1e30f;
            s_cur[j][3] = (c0 + 1 < len) ? s_cur[j][3] * scl : -1e30f;
            mx0 = fmaxf(mx0, fmaxf(s_cur[j][0], s_cur[j][1]));
            mx1 = fmaxf(mx1, fmaxf(s_cur[j][2], s_cur[j][3]));
        }
        mx0 = fmaxf(mx0, __shfl_xor_sync(0xffffffffu, mx0, 1));
        mx0 = fmaxf(mx0, __shfl_xor_sync(0xffffffffu, mx0, 2));
        mx1 = fmaxf(mx1, __shfl_xor_sync(0xffffffffu, mx1, 1));
        mx1 = fmaxf(mx1, __shfl_xor_sync(0xffffffffu, mx1, 2));

        float mn0 = fmaxf(m0, mx0), mn1 = fmaxf(m1, mx1);
        float al0 = exp2f(m0 - mn0), al1 = exp2f(m1 - mn1);

        u32 pf[8][2];
#pragma unroll
        for (int j = 0; j < 8; j++) {
            pf[j][0] = ex2_h2(h2u(s_cur[j][0] - mn0, s_cur[j][1] - mn0));
            pf[j][1] = ex2_h2(h2u(s_cur[j][2] - mn1, s_cur[j][3] - mn1));
        }

        // row sums of P via tensor core (B = ones)
        float lacc[4] = {0.f, 0.f, 0.f, 0.f};
#pragma unroll
        for (int k2 = 0; k2 < 4; k2++) {
            uint4 a;
            a.x = pf[2 * k2][0];     a.y = pf[2 * k2][1];
            a.z = pf[2 * k2 + 1][0]; a.w = pf[2 * k2 + 1][1];
            mma16816(lacc, a, ONES2, ONES2);
        }
        l0 = l0 * al0 + lacc[0];
        l1 = l1 * al1 + lacc[2];
        m0 = mn0; m1 = mn1;
#pragma unroll
        for (int j2 = 0; j2 < 16; j2++) {
            o[j2][0] *= al0; o[j2][1] *= al0;
            o[j2][2] *= al1; o[j2][3] *= al1;
        }

        // ---- O += P V (V slot kt&1) ----
        const u32 vbase = smb + (u32)((FA_VOFF + (kt & 1) * FA_TILE_HALFS) * 2);
#pragma unroll
        for (int k2 = 0; k2 < 4; k2++) {
            uint4 a;
            a.x = pf[2 * k2][0];     a.y = pf[2 * k2][1];
            a.z = pf[2 * k2 + 1][0]; a.w = pf[2 * k2 + 1][1];
#pragma unroll
            for (int np = 0; np < 8; np++) {
                uint4 bf = ldsm_x4_t(vbase + (u32)((((16 * k2 + vrow) * 128) +
                                     (((2 * np + vcol) ^ vx) << 3)) << 1));
                mma16816(o[2 * np],     a, bf.x, bf.y);
                mma16816(o[2 * np + 1], a, bf.z, bf.w);
            }
        }

        __syncthreads();    // all PV reads of V slot kt&1 done
        if (kt + 2 < nkt) {
            fa_load_tile(smb + (u32)((FA_VOFF + (kt & 1) * FA_TILE_HALFS) * 2),
                         vg, kt + 2, t);
            CP_COMMIT();
        }
        if (kt + 1 < nkt) {
#pragma unroll
            for (int j = 0; j < 8; j++)
#pragma unroll
                for (int e = 0; e < 4; e++) s_cur[j][e] = s_next[j][e];
        }
    }

    const float il0 = 1.f / l0, il1 = 1.f / l1;
    const int r0 = s0 + 16 * warp + (lane >> 2);
    __half* ob = g_attnh + (size_t)(b * SS) * DD + h * DHD;
#pragma unroll
    for (int j2 = 0; j2 < 16; j2++) {
        int col = 8 * j2 + 2 * (lane & 3);
        *(__half2*)(ob + (size_t)r0 * DD + col) =
            __floats2half2_rn(o[j2][0] * il0, o[j2][1] * il0);
        *(__half2*)(ob + (size_t)(r0 + 8) * DD + col) =
            __floats2half2_rn(o[j2][2] * il1, o[j2][3] * il1);
    }
}

// ---------------------------------------------------------------------------
// Launch: R12 graph (measured best) + length-aware dead-work elimination.
//   M (stream 0): conv(wq,wk,x) -> QK gemm -> norm -> [eB] FA -> [eC] O gemm
//   B:            conv(wv) -> [eX] V gemm -> eB
//   C:            conv(wo) -> eC
// ---------------------------------------------------------------------------
extern "C" void kernel_launch(void* const* d_in, const int* in_sizes, int n_in,
                              void* d_out, int out_size) {
    const float* x     = (const float*)d_in[0];
    const float* wq_s  = (const float*)d_in[1];
    const float* wk_s  = (const float*)d_in[2];
    const float* wv_s  = (const float*)d_in[3];
    const float* wo_s  = (const float*)d_in[4];
    const float* qn_w  = (const float*)d_in[5];
    const float* kn_w  = (const float*)d_in[6];
    const float* cosT  = (const float*)d_in[7];
    const float* sinT  = (const float*)d_in[8];
    const int*   wq    = (const int*)d_in[9];
    const int*   wk    = (const int*)d_in[10];
    const int*   wv    = (const int*)d_in[11];
    const int*   wo    = (const int*)d_in[12];
    const int*   lens  = (const int*)d_in[13];
    float*       out   = (float*)d_out;

    static cudaStream_t sB = nullptr, sC = nullptr;
    static cudaEvent_t e0 = nullptr, eX = nullptr, eB = nullptr, eC = nullptr;
    if (sB == nullptr) {
        cudaStreamCreateWithFlags(&sB, cudaStreamNonBlocking);
        cudaStreamCreateWithFlags(&sC, cudaStreamNonBlocking);
        cudaEventCreateWithFlags(&e0, cudaEventDisableTiming);
        cudaEventCreateWithFlags(&eX, cudaEventDisableTiming);
        cudaEventCreateWithFlags(&eB, cudaEventDisableTiming);
        cudaEventCreateWithFlags(&eC, cudaEventDisableTiming);
        cudaFuncSetAttribute(hgemm_qk,
                             cudaFuncAttributeMaxDynamicSharedMemorySize, HG_BYTES);
        cudaFuncSetAttribute(hgemm_v,
                             cudaFuncAttributeMaxDynamicSharedMemorySize, HG_BYTES);
        cudaFuncSetAttribute(hgemm_o,
                             cudaFuncAttributeMaxDynamicSharedMemorySize, HG_BYTES);
        cudaFuncSetAttribute(flash_attn,
                             cudaFuncAttributeMaxDynamicSharedMemorySize, FA_BYTES);
    }

    const int cgx = (DD * DD) / (256 * 16);   // 1024 blocks per tensor

    // fork side branches off the captured (legacy) stream
    cudaEventRecord(e0, 0);
    cudaStreamWaitEvent(sB, e0, 0);
    cudaStreamWaitEvent(sC, e0, 0);

    // M: wq, wk, x converts
    convert_all<<<dim3(cgx, 3), 256>>>(wq, wk, wv, wo, wq_s, wk_s, wv_s, wo_s,
                                       x, 0, 1, 4);
    cudaEventRecord(eX, 0);   // wq/wk/x converted

    // B: wv convert, then V gemm (after x ready)
    convert_all<<<dim3(cgx, 1), 256, 0, sB>>>(wq, wk, wv, wo, wq_s, wk_s, wv_s,
                                              wo_s, x, 2, 2, 2);
    cudaStreamWaitEvent(sB, eX, 0);
    hgemm_v<<<dim3(16, 16), 256, HG_BYTES, sB>>>(lens);
    cudaEventRecord(eB, sB);

    // C: wo convert
    convert_all<<<dim3(cgx, 1), 256, 0, sC>>>(wq, wk, wv, wo, wq_s, wk_s, wv_s,
                                              wo_s, x, 3, 3, 3);
    cudaEventRecord(eC, sC);

    // M: QK gemm -> norm+rope
    hgemm_qk<<<dim3(16, 16, 2), 256, HG_BYTES>>>(lens);
    norm_rope<<<dim3(MM, 2), 256>>>(cosT, sinT, qn_w, kn_w, lens);

    // M: FA needs V (eB)
    cudaStreamWaitEvent(0, eB, 0);
    flash_attn<<<dim3(SS / 64, HH, BB), 128, FA_BYTES>>>(lens);

    // M: O gemm needs wo (eC)
    cudaStreamWaitEvent(0, eC, 0);
    hgemm_o<<<dim3(16, 16), 256, HG_BYTES>>>(out);
}